// round 10
// baseline (speedup 1.0000x reference)
#include <cuda_runtime.h>

#define MARGIN 0.5f

// Scratch accumulators (no device allocation allowed -> __device__ globals).
// Zero at module load; last block re-zeros each call (graph-replay safe).
__device__ float        g_total;
__device__ unsigned int g_count;
__device__ unsigned int g_arrive;

// ---------------------------------------------------------------------------
// Fast path: C=64, P=16, N=48, B%4==0. One warp = one QUAD of problems.
// KEY CHANGE vs round 9: the data-dependent score gathers no longer hit DRAM.
// The quad's 4 score rows are 256 contiguous floats -> loaded coalesced as
// 2x LDG.128 per lane IN PARALLEL with the index loads (one DRAM round-trip
// total), staged to a warp-private smem region, then the 8 gathers are LDS
// (~29cyc) instead of a second dependent DRAM trip (~600cyc).
// Per-pair register layout (rounds 6-9):
//   nA : even-prob neg slots 0-31 (all lanes)
//   nBm: lanes 0-15 = even-prob slots 32-47; lanes 16-31 = odd-prob slots 0-15
//   nC : odd-prob neg slots 16-47 (all lanes)
//   pvm: lanes 0-15 = MARGIN - even-prob pos; 16-31 = odd-prob (inv -> -1e30,
//        relu-self-masking, margin pre-folded)
// ---------------------------------------------------------------------------
#define FWARPS 8
#define FTHREADS (FWARPS * 32)

__global__ void __launch_bounds__(FTHREADS)
mpcl_fast_kernel(const float* __restrict__ scores,
                 const int*   __restrict__ pos_indices,
                 const int*   __restrict__ neg_indices,
                 const int*   __restrict__ pos_counts,
                 const int*   __restrict__ neg_counts,
                 float*       __restrict__ out,
                 int nQuads)
{
    __shared__ float    s_rows[FWARPS][256];   // 4 score rows per warp
    __shared__ float    s_tot[FWARPS];
    __shared__ unsigned s_cnt[FWARPS];

    const int warp = threadIdx.x >> 5;
    const int lane = threadIdx.x & 31;
    const int q    = blockIdx.x * FWARPS + warp;

    float acc0 = 0.0f, acc1 = 0.0f, acc2 = 0.0f, acc3 = 0.0f;
    unsigned cnt = 0u;

    if (q < nQuads) {
        const int b0    = q * 4;
        const bool lo16 = (lane < 16);
        const int  slot = lane & 15;

        // ---- ONE batch of independent loads: counts, indices, full rows ----
        const int2 pcA = *reinterpret_cast<const int2*>(pos_counts + b0);
        const int2 pcB = *reinterpret_cast<const int2*>(pos_counts + b0 + 2);
        const int2 ncA = *reinterpret_cast<const int2*>(neg_counts + b0);
        const int2 ncB = *reinterpret_cast<const int2*>(neg_counts + b0 + 2);

        const int* nn = neg_indices + (size_t)b0 * 48;  // 192 contiguous ints
        const int* pp = pos_indices + (size_t)b0 * 16;  // 64 contiguous ints
        const int jA0 = nn[lane];
        const int jA1 = nn[lane + 32];
        const int jA2 = nn[lane + 64];
        const int jB0 = nn[lane + 96];
        const int jB1 = nn[lane + 128];
        const int jB2 = nn[lane + 160];
        const int jPA = pp[lane];
        const int jPB = pp[lane + 32];

        // rows: 256 floats, 256B-aligned (b0*64*4 is a multiple of 1024)
        const float4* src = reinterpret_cast<const float4*>(
            scores + (size_t)b0 * 64);
        const float4 v0 = src[lane];
        const float4 v1 = src[lane + 32];

        // ---- stage rows to warp-private smem, then LDS "gathers" ----
        float4* dst = reinterpret_cast<float4*>(s_rows[warp]);
        dst[lane]      = v0;
        dst[lane + 32] = v1;
        __syncwarp();

        const float* sw   = s_rows[warp];
        const int    offA = lo16 ? 0 : 64;     // mixed row, pair A
        const int    offB = lo16 ? 128 : 192;  // mixed row, pair B
        const float gA0 = sw[jA0];             // row b0
        const float gA1 = sw[offA + jA1];
        const float gA2 = sw[64 + jA2];        // row b0+1
        const float gPA = sw[offA + jPA];
        const float gB0 = sw[128 + jB0];       // row b0+2
        const float gB1 = sw[offB + jB1];
        const float gB2 = sw[192 + jB2];       // row b0+3
        const float gPB = sw[offB + jPB];

        // ---- pair A masks (problems b0, b0+1) ----
        const int pc0 = pcA.x, pc1 = pcA.y;
        const int nc0 = ncA.x, nc1 = ncA.y;
        const float nA_A  = (lane < nc0) ? gA0 : -1e30f;
        const bool  bvA   = lo16 ? (lane + 32 < nc0) : (lane - 16 < nc1);
        const float nBmA  = bvA ? gA1 : -1e30f;
        const float nB0_A = lo16 ? nBmA : -1e30f;
        const float nB1_A = lo16 ? -1e30f : nBmA;
        const float nC_A  = (lane + 16 < nc1) ? gA2 : -1e30f;
        const int   pcOwnA = lo16 ? pc0 : pc1;
        const float pvmA   = (slot < pcOwnA) ? (MARGIN - gPA) : -1e30f;

        // ---- pair B masks (problems b0+2, b0+3) ----
        const int pc2 = pcB.x, pc3 = pcB.y;
        const int nc2 = ncB.x, nc3 = ncB.y;
        const float nA_B  = (lane < nc2) ? gB0 : -1e30f;
        const bool  bvB   = lo16 ? (lane + 32 < nc2) : (lane - 16 < nc3);
        const float nBmB  = bvB ? gB1 : -1e30f;
        const float nB0_B = lo16 ? nBmB : -1e30f;
        const float nB1_B = lo16 ? -1e30f : nBmB;
        const float nC_B  = (lane + 16 < nc3) ? gB2 : -1e30f;
        const int   pcOwnB = lo16 ? pc2 : pc3;
        const float pvmB   = (slot < pcOwnB) ? (MARGIN - gPB) : -1e30f;

        cnt = (unsigned)(pc0 * nc0) + (unsigned)(pc1 * nc1)
            + (unsigned)(pc2 * nc2) + (unsigned)(pc3 * nc3);

        // ---- problem b0 (no nc guard: masked negs give exact 0) ----
        for (int pg = 0; pg < pc0; pg += 4) {
            const float a0 = __shfl_sync(0xffffffffu, pvmA, pg + 0);
            const float a1 = __shfl_sync(0xffffffffu, pvmA, pg + 1);
            const float a2 = __shfl_sync(0xffffffffu, pvmA, pg + 2);
            const float a3 = __shfl_sync(0xffffffffu, pvmA, pg + 3);
            acc0 += fmaxf(a0 + nA_A, 0.0f) + fmaxf(a0 + nB0_A, 0.0f);
            acc1 += fmaxf(a1 + nA_A, 0.0f) + fmaxf(a1 + nB0_A, 0.0f);
            acc2 += fmaxf(a2 + nA_A, 0.0f) + fmaxf(a2 + nB0_A, 0.0f);
            acc3 += fmaxf(a3 + nA_A, 0.0f) + fmaxf(a3 + nB0_A, 0.0f);
        }
        // ---- problem b0+1 ----
        for (int pg = 0; pg < pc1; pg += 4) {
            const float a0 = __shfl_sync(0xffffffffu, pvmA, 16 + pg + 0);
            const float a1 = __shfl_sync(0xffffffffu, pvmA, 16 + pg + 1);
            const float a2 = __shfl_sync(0xffffffffu, pvmA, 16 + pg + 2);
            const float a3 = __shfl_sync(0xffffffffu, pvmA, 16 + pg + 3);
            acc0 += fmaxf(a0 + nB1_A, 0.0f) + fmaxf(a0 + nC_A, 0.0f);
            acc1 += fmaxf(a1 + nB1_A, 0.0f) + fmaxf(a1 + nC_A, 0.0f);
            acc2 += fmaxf(a2 + nB1_A, 0.0f) + fmaxf(a2 + nC_A, 0.0f);
            acc3 += fmaxf(a3 + nB1_A, 0.0f) + fmaxf(a3 + nC_A, 0.0f);
        }
        // ---- problem b0+2 ----
        for (int pg = 0; pg < pc2; pg += 4) {
            const float a0 = __shfl_sync(0xffffffffu, pvmB, pg + 0);
            const float a1 = __shfl_sync(0xffffffffu, pvmB, pg + 1);
            const float a2 = __shfl_sync(0xffffffffu, pvmB, pg + 2);
            const float a3 = __shfl_sync(0xffffffffu, pvmB, pg + 3);
            acc0 += fmaxf(a0 + nA_B, 0.0f) + fmaxf(a0 + nB0_B, 0.0f);
            acc1 += fmaxf(a1 + nA_B, 0.0f) + fmaxf(a1 + nB0_B, 0.0f);
            acc2 += fmaxf(a2 + nA_B, 0.0f) + fmaxf(a2 + nB0_B, 0.0f);
            acc3 += fmaxf(a3 + nA_B, 0.0f) + fmaxf(a3 + nB0_B, 0.0f);
        }
        // ---- problem b0+3 ----
        for (int pg = 0; pg < pc3; pg += 4) {
            const float a0 = __shfl_sync(0xffffffffu, pvmB, 16 + pg + 0);
            const float a1 = __shfl_sync(0xffffffffu, pvmB, 16 + pg + 1);
            const float a2 = __shfl_sync(0xffffffffu, pvmB, 16 + pg + 2);
            const float a3 = __shfl_sync(0xffffffffu, pvmB, 16 + pg + 3);
            acc0 += fmaxf(a0 + nB1_B, 0.0f) + fmaxf(a0 + nC_B, 0.0f);
            acc1 += fmaxf(a1 + nB1_B, 0.0f) + fmaxf(a1 + nC_B, 0.0f);
            acc2 += fmaxf(a2 + nB1_B, 0.0f) + fmaxf(a2 + nC_B, 0.0f);
            acc3 += fmaxf(a3 + nB1_B, 0.0f) + fmaxf(a3 + nC_B, 0.0f);
        }
    }

    float accs = (acc0 + acc1) + (acc2 + acc3);
    #pragma unroll
    for (int o = 16; o > 0; o >>= 1)
        accs += __shfl_xor_sync(0xffffffffu, accs, o);

    if (lane == 0) { s_tot[warp] = accs; s_cnt[warp] = cnt; }
    __syncthreads();

    if (threadIdx.x == 0) {
        float    t = 0.0f;
        unsigned c = 0u;
        #pragma unroll
        for (int i = 0; i < FWARPS; i++) { t += s_tot[i]; c += s_cnt[i]; }
        // Fence-free finalize (no CCTL.IVALL): release REDs + acq_rel ticket.
        asm volatile("red.add.release.gpu.f32 [%0], %1;"
                     :: "l"(&g_total), "f"(t) : "memory");
        asm volatile("red.add.release.gpu.u32 [%0], %1;"
                     :: "l"(&g_count), "r"(c) : "memory");
        unsigned ticket;
        asm volatile("atom.add.acq_rel.gpu.u32 %0, [%1], %2;"
                     : "=r"(ticket) : "l"(&g_arrive), "r"(1u) : "memory");
        if (ticket == (unsigned)gridDim.x - 1u) {
            float tv; unsigned cv;
            asm volatile("ld.acquire.gpu.f32 %0, [%1];"
                         : "=f"(tv) : "l"(&g_total) : "memory");
            asm volatile("ld.acquire.gpu.u32 %0, [%1];"
                         : "=r"(cv) : "l"(&g_count) : "memory");
            out[0] = (cv > 0u) ? (tv / (float)cv) : 0.0f;
            g_total = 0.0f; g_count = 0u; g_arrive = 0u;
        }
    }
}

// ---------------------------------------------------------------------------
// Generic fallback (round-5 proven kernel), used only if shape differs.
// ---------------------------------------------------------------------------
#define GWARPS 16
#define GTHREADS (GWARPS * 32)

__global__ void __launch_bounds__(GTHREADS, 4)
mpcl_generic_kernel(const float* __restrict__ scores,
                    const int*   __restrict__ pos_indices,
                    const int*   __restrict__ neg_indices,
                    const int*   __restrict__ pos_counts,
                    const int*   __restrict__ neg_counts,
                    float*       __restrict__ out,
                    int B, int C, int P, int N, int nPairs)
{
    __shared__ float    s_tot[GWARPS];
    __shared__ unsigned s_cnt[GWARPS];

    const int warp    = threadIdx.x >> 5;
    const int lane    = threadIdx.x & 31;
    const int gwarp   = blockIdx.x * GWARPS + warp;
    const int wstride = gridDim.x * GWARPS;
    const bool loHalf = (lane < 16);

    float    acc0 = 0.0f, acc1 = 0.0f;
    unsigned cnt  = 0u;

    for (int q = gwarp; q < nPairs; q += wstride) {
        const int  b0   = q * 2;
        const int  b1   = b0 + 1;
        const bool has1 = (b1 < B);

        const int pc0 = min(pos_counts[b0], 16);
        const int nc0 = neg_counts[b0];
        const int pc1 = has1 ? min(pos_counts[b1], 16) : 0;
        const int nc1 = has1 ? neg_counts[b1]          : 0;

        const float* s0  = scores + (size_t)b0 * (size_t)C;
        const float* s1  = scores + (size_t)b1 * (size_t)C;
        const int*   n0p = neg_indices + (size_t)b0 * (size_t)N;
        const int*   n1p = neg_indices + (size_t)b1 * (size_t)N;

        const int    slot  = lane & 15;
        const bool   myOk  = loHalf || has1;
        const int*   pbase = loHalf ? (pos_indices + (size_t)b0 * (size_t)P)
                                    : (pos_indices + (size_t)b1 * (size_t)P);
        const int    jp    = (myOk && slot < P) ? pbase[slot] : 0;
        const float* sbase = loHalf ? s0 : s1;
        float pv = myOk ? sbase[jp] : 1e30f;
        const int pcOwn = loHalf ? pc0 : pc1;
        pv = (slot < pcOwn) ? pv : 1e30f;

        const int j00 = (lane      < N) ? n0p[lane]      : 0;
        const int j01 = (lane + 32 < N) ? n0p[lane + 32] : 0;
        float n00 = (lane      < nc0) ? s0[j00] : -1e30f;
        float n01 = (lane + 32 < nc0) ? s0[j01] : -1e30f;

        float n10 = -1e30f, n11 = -1e30f;
        if (has1) {
            const int j10 = (lane      < N) ? n1p[lane]      : 0;
            const int j11 = (lane + 32 < N) ? n1p[lane + 32] : 0;
            n10 = (lane      < nc1) ? s1[j10] : -1e30f;
            n11 = (lane + 32 < nc1) ? s1[j11] : -1e30f;
        }

        cnt += (unsigned)(pc0 * nc0) + (unsigned)(pc1 * nc1);

        const int it0 = (nc0 > 0) ? pc0 : 0;
        for (int pg = 0; pg < it0; pg += 4) {
            const float x0 = __shfl_sync(0xffffffffu, pv, pg + 0);
            const float x1 = __shfl_sync(0xffffffffu, pv, pg + 1);
            const float x2 = __shfl_sync(0xffffffffu, pv, pg + 2);
            const float x3 = __shfl_sync(0xffffffffu, pv, pg + 3);
            const float a0 = MARGIN - x0, a1 = MARGIN - x1;
            const float a2 = MARGIN - x2, a3 = MARGIN - x3;
            acc0 += fmaxf(a0 + n00, 0.0f) + fmaxf(a1 + n00, 0.0f)
                  + fmaxf(a2 + n00, 0.0f) + fmaxf(a3 + n00, 0.0f);
            acc1 += fmaxf(a0 + n01, 0.0f) + fmaxf(a1 + n01, 0.0f)
                  + fmaxf(a2 + n01, 0.0f) + fmaxf(a3 + n01, 0.0f);
        }
        const int it1 = (nc1 > 0) ? pc1 : 0;
        for (int pg = 0; pg < it1; pg += 4) {
            const float x0 = __shfl_sync(0xffffffffu, pv, 16 + pg + 0);
            const float x1 = __shfl_sync(0xffffffffu, pv, 16 + pg + 1);
            const float x2 = __shfl_sync(0xffffffffu, pv, 16 + pg + 2);
            const float x3 = __shfl_sync(0xffffffffu, pv, 16 + pg + 3);
            const float a0 = MARGIN - x0, a1 = MARGIN - x1;
            const float a2 = MARGIN - x2, a3 = MARGIN - x3;
            acc0 += fmaxf(a0 + n10, 0.0f) + fmaxf(a1 + n10, 0.0f)
                  + fmaxf(a2 + n10, 0.0f) + fmaxf(a3 + n10, 0.0f);
            acc1 += fmaxf(a0 + n11, 0.0f) + fmaxf(a1 + n11, 0.0f)
                  + fmaxf(a2 + n11, 0.0f) + fmaxf(a3 + n11, 0.0f);
        }
    }

    float accs = acc0 + acc1;
    #pragma unroll
    for (int o = 16; o > 0; o >>= 1)
        accs += __shfl_xor_sync(0xffffffffu, accs, o);

    if (lane == 0) { s_tot[warp] = accs; s_cnt[warp] = cnt; }
    __syncthreads();

    if (threadIdx.x == 0) {
        float    t = 0.0f;
        unsigned c = 0u;
        #pragma unroll
        for (int i = 0; i < GWARPS; i++) { t += s_tot[i]; c += s_cnt[i]; }
        asm volatile("red.add.release.gpu.f32 [%0], %1;"
                     :: "l"(&g_total), "f"(t) : "memory");
        asm volatile("red.add.release.gpu.u32 [%0], %1;"
                     :: "l"(&g_count), "r"(c) : "memory");
        unsigned ticket;
        asm volatile("atom.add.acq_rel.gpu.u32 %0, [%1], %2;"
                     : "=r"(ticket) : "l"(&g_arrive), "r"(1u) : "memory");
        if (ticket == (unsigned)gridDim.x - 1u) {
            float tv; unsigned cv;
            asm volatile("ld.acquire.gpu.f32 %0, [%1];"
                         : "=f"(tv) : "l"(&g_total) : "memory");
            asm volatile("ld.acquire.gpu.u32 %0, [%1];"
                         : "=r"(cv) : "l"(&g_count) : "memory");
            out[0] = (cv > 0u) ? (tv / (float)cv) : 0.0f;
            g_total = 0.0f; g_count = 0u; g_arrive = 0u;
        }
    }
}

extern "C" void kernel_launch(void* const* d_in, const int* in_sizes, int n_in,
                              void* d_out, int out_size)
{
    const float* scores      = (const float*)d_in[0];
    const int*   pos_indices = (const int*)  d_in[1];
    const int*   neg_indices = (const int*)  d_in[2];
    const int*   pos_counts  = (const int*)  d_in[3];
    const int*   neg_counts  = (const int*)  d_in[4];
    float*       out         = (float*)d_out;

    const int B = in_sizes[3];
    const int C = in_sizes[0] / B;
    const int P = in_sizes[1] / B;
    const int N = in_sizes[2] / B;

    if (C == 64 && P == 16 && N == 48 && (B % 4) == 0) {
        const int nQuads = B / 4;
        const int blocks = (nQuads + FWARPS - 1) / FWARPS;
        mpcl_fast_kernel<<<blocks, FTHREADS>>>(
            scores, pos_indices, neg_indices, pos_counts, neg_counts, out,
            nQuads);
    } else {
        const int nPairs = (B + 1) / 2;
        int blocks = (nPairs + GWARPS * 2 - 1) / (GWARPS * 2);
        if (blocks > 592) blocks = 592;
        if (blocks < 1)   blocks = 1;
        mpcl_generic_kernel<<<blocks, GTHREADS>>>(
            scores, pos_indices, neg_indices, pos_counts, neg_counts, out,
            B, C, P, N, nPairs);
    }
}

// round 11
// speedup vs baseline: 1.0276x; 1.0276x over previous
#include <cuda_runtime.h>

#define MARGIN 0.5f

// Scratch accumulators (no device allocation allowed -> __device__ globals).
// Zero at module load; last block re-zeros each call (graph-replay safe).
__device__ float        g_total;
__device__ unsigned int g_count;
__device__ unsigned int g_arrive;

// ---------------------------------------------------------------------------
// Fast path: C=64, P=16, N=48, B%32==0.
// BLOCK-COOPERATIVE STAGING: a 256-thread block owns 32 problems and stages
// scores (8KB), neg indices (6KB), pos indices (2KB) and counts (256B) into
// smem with ~5 coalesced LDG.128 per thread -- ONE DRAM round-trip, ~3x fewer
// L1TEX wavefronts than the per-warp narrow-LDG versions (rounds 7-10, all
// plateaued at ~13us from L1TEX queue contention). Compute phase = the proven
// round-9 quad-per-warp kernel with every memory read turned into LDS.
// Per-pair register layout (rounds 6-10):
//   nA : even-prob neg slots 0-31 (all lanes)
//   nBm: lanes 0-15 = even-prob slots 32-47; lanes 16-31 = odd-prob slots 0-15
//   nC : odd-prob neg slots 16-47 (all lanes)
//   pvm: lanes 0-15 = MARGIN - even-prob pos; 16-31 = odd-prob (inv -> -1e30,
//        relu-self-masking, margin pre-folded)
// ---------------------------------------------------------------------------
#define FWARPS 8
#define FTHREADS 256

__global__ void __launch_bounds__(FTHREADS)
mpcl_fast_kernel(const float* __restrict__ scores,
                 const int*   __restrict__ pos_indices,
                 const int*   __restrict__ neg_indices,
                 const int*   __restrict__ pos_counts,
                 const int*   __restrict__ neg_counts,
                 float*       __restrict__ out)
{
    __shared__ float    s_scores[32 * 64];   // 8 KB
    __shared__ int      s_nidx[32 * 48];     // 6 KB
    __shared__ int      s_pidx[32 * 16];     // 2 KB
    __shared__ int      s_pc[32];
    __shared__ int      s_nc[32];
    __shared__ float    s_tot[FWARPS];
    __shared__ unsigned s_cnt[FWARPS];

    const int tid  = threadIdx.x;
    const int warp = tid >> 5;
    const int lane = tid & 31;
    const int base = blockIdx.x * 32;        // first problem of this block

    // ---- staging: all wide, all coalesced, all independent ----
    {
        const float4* sc4 = reinterpret_cast<const float4*>(
            scores + (size_t)base * 64);     // 512 float4
        float4* ss4 = reinterpret_cast<float4*>(s_scores);
        ss4[tid]       = sc4[tid];
        ss4[tid + 256] = sc4[tid + 256];

        const int4* ni4 = reinterpret_cast<const int4*>(
            neg_indices + (size_t)base * 48);  // 384 int4
        int4* sn4 = reinterpret_cast<int4*>(s_nidx);
        sn4[tid] = ni4[tid];
        if (tid < 128) sn4[tid + 256] = ni4[tid + 256];

        const int4* pi4 = reinterpret_cast<const int4*>(
            pos_indices + (size_t)base * 16);  // 128 int4
        int4* sp4 = reinterpret_cast<int4*>(s_pidx);
        if (tid < 128) sp4[tid] = pi4[tid];

        if (tid < 32)                 s_pc[tid]      = pos_counts[base + tid];
        else if (tid < 64)            s_nc[tid - 32] = neg_counts[base + tid - 32];
    }
    __syncthreads();

    // ---- compute: quad per warp, all reads from smem ----
    float acc0 = 0.0f, acc1 = 0.0f, acc2 = 0.0f, acc3 = 0.0f;
    unsigned cnt = 0u;
    {
        const bool lo16 = (lane < 16);
        const int  slot = lane & 15;
        const int  qo   = warp * 4;          // local problem offset

        const int pc0 = s_pc[qo],     pc1 = s_pc[qo + 1];
        const int pc2 = s_pc[qo + 2], pc3 = s_pc[qo + 3];
        const int nc0 = s_nc[qo],     nc1 = s_nc[qo + 1];
        const int nc2 = s_nc[qo + 2], nc3 = s_nc[qo + 3];

        const int*   nn = s_nidx + warp * 192;
        const int*   pp = s_pidx + warp * 64;
        const float* sw = s_scores + warp * 256;

        const int jA0 = nn[lane];
        const int jA1 = nn[lane + 32];
        const int jA2 = nn[lane + 64];
        const int jB0 = nn[lane + 96];
        const int jB1 = nn[lane + 128];
        const int jB2 = nn[lane + 160];
        const int jPA = pp[lane];
        const int jPB = pp[lane + 32];

        const int offA = lo16 ? 0 : 64;      // mixed row, pair A
        const int offB = lo16 ? 128 : 192;   // mixed row, pair B
        const float gA0 = sw[jA0];           // row b0
        const float gA1 = sw[offA + jA1];
        const float gA2 = sw[64 + jA2];      // row b0+1
        const float gPA = sw[offA + jPA];
        const float gB0 = sw[128 + jB0];     // row b0+2
        const float gB1 = sw[offB + jB1];
        const float gB2 = sw[192 + jB2];     // row b0+3
        const float gPB = sw[offB + jPB];

        // ---- pair A masks (problems base+qo, +1) ----
        const float nA_A  = (lane < nc0) ? gA0 : -1e30f;
        const bool  bvA   = lo16 ? (lane + 32 < nc0) : (lane - 16 < nc1);
        const float nBmA  = bvA ? gA1 : -1e30f;
        const float nB0_A = lo16 ? nBmA : -1e30f;
        const float nB1_A = lo16 ? -1e30f : nBmA;
        const float nC_A  = (lane + 16 < nc1) ? gA2 : -1e30f;
        const int   pcOwnA = lo16 ? pc0 : pc1;
        const float pvmA   = (slot < pcOwnA) ? (MARGIN - gPA) : -1e30f;

        // ---- pair B masks (problems base+qo+2, +3) ----
        const float nA_B  = (lane < nc2) ? gB0 : -1e30f;
        const bool  bvB   = lo16 ? (lane + 32 < nc2) : (lane - 16 < nc3);
        const float nBmB  = bvB ? gB1 : -1e30f;
        const float nB0_B = lo16 ? nBmB : -1e30f;
        const float nB1_B = lo16 ? -1e30f : nBmB;
        const float nC_B  = (lane + 16 < nc3) ? gB2 : -1e30f;
        const int   pcOwnB = lo16 ? pc2 : pc3;
        const float pvmB   = (slot < pcOwnB) ? (MARGIN - gPB) : -1e30f;

        cnt = (unsigned)(pc0 * nc0) + (unsigned)(pc1 * nc1)
            + (unsigned)(pc2 * nc2) + (unsigned)(pc3 * nc3);

        // ---- problem 0 (no nc guard: masked negs give exact 0) ----
        for (int pg = 0; pg < pc0; pg += 4) {
            const float a0 = __shfl_sync(0xffffffffu, pvmA, pg + 0);
            const float a1 = __shfl_sync(0xffffffffu, pvmA, pg + 1);
            const float a2 = __shfl_sync(0xffffffffu, pvmA, pg + 2);
            const float a3 = __shfl_sync(0xffffffffu, pvmA, pg + 3);
            acc0 += fmaxf(a0 + nA_A, 0.0f) + fmaxf(a0 + nB0_A, 0.0f);
            acc1 += fmaxf(a1 + nA_A, 0.0f) + fmaxf(a1 + nB0_A, 0.0f);
            acc2 += fmaxf(a2 + nA_A, 0.0f) + fmaxf(a2 + nB0_A, 0.0f);
            acc3 += fmaxf(a3 + nA_A, 0.0f) + fmaxf(a3 + nB0_A, 0.0f);
        }
        // ---- problem 1 ----
        for (int pg = 0; pg < pc1; pg += 4) {
            const float a0 = __shfl_sync(0xffffffffu, pvmA, 16 + pg + 0);
            const float a1 = __shfl_sync(0xffffffffu, pvmA, 16 + pg + 1);
            const float a2 = __shfl_sync(0xffffffffu, pvmA, 16 + pg + 2);
            const float a3 = __shfl_sync(0xffffffffu, pvmA, 16 + pg + 3);
            acc0 += fmaxf(a0 + nB1_A, 0.0f) + fmaxf(a0 + nC_A, 0.0f);
            acc1 += fmaxf(a1 + nB1_A, 0.0f) + fmaxf(a1 + nC_A, 0.0f);
            acc2 += fmaxf(a2 + nB1_A, 0.0f) + fmaxf(a2 + nC_A, 0.0f);
            acc3 += fmaxf(a3 + nB1_A, 0.0f) + fmaxf(a3 + nC_A, 0.0f);
        }
        // ---- problem 2 ----
        for (int pg = 0; pg < pc2; pg += 4) {
            const float a0 = __shfl_sync(0xffffffffu, pvmB, pg + 0);
            const float a1 = __shfl_sync(0xffffffffu, pvmB, pg + 1);
            const float a2 = __shfl_sync(0xffffffffu, pvmB, pg + 2);
            const float a3 = __shfl_sync(0xffffffffu, pvmB, pg + 3);
            acc0 += fmaxf(a0 + nA_B, 0.0f) + fmaxf(a0 + nB0_B, 0.0f);
            acc1 += fmaxf(a1 + nA_B, 0.0f) + fmaxf(a1 + nB0_B, 0.0f);
            acc2 += fmaxf(a2 + nA_B, 0.0f) + fmaxf(a2 + nB0_B, 0.0f);
            acc3 += fmaxf(a3 + nA_B, 0.0f) + fmaxf(a3 + nB0_B, 0.0f);
        }
        // ---- problem 3 ----
        for (int pg = 0; pg < pc3; pg += 4) {
            const float a0 = __shfl_sync(0xffffffffu, pvmB, 16 + pg + 0);
            const float a1 = __shfl_sync(0xffffffffu, pvmB, 16 + pg + 1);
            const float a2 = __shfl_sync(0xffffffffu, pvmB, 16 + pg + 2);
            const float a3 = __shfl_sync(0xffffffffu, pvmB, 16 + pg + 3);
            acc0 += fmaxf(a0 + nB1_B, 0.0f) + fmaxf(a0 + nC_B, 0.0f);
            acc1 += fmaxf(a1 + nB1_B, 0.0f) + fmaxf(a1 + nC_B, 0.0f);
            acc2 += fmaxf(a2 + nB1_B, 0.0f) + fmaxf(a2 + nC_B, 0.0f);
            acc3 += fmaxf(a3 + nB1_B, 0.0f) + fmaxf(a3 + nC_B, 0.0f);
        }
    }

    float accs = (acc0 + acc1) + (acc2 + acc3);
    #pragma unroll
    for (int o = 16; o > 0; o >>= 1)
        accs += __shfl_xor_sync(0xffffffffu, accs, o);

    if (lane == 0) { s_tot[warp] = accs; s_cnt[warp] = cnt; }
    __syncthreads();

    if (tid == 0) {
        float    t = 0.0f;
        unsigned c = 0u;
        #pragma unroll
        for (int i = 0; i < FWARPS; i++) { t += s_tot[i]; c += s_cnt[i]; }
        // Fence-free finalize (no CCTL.IVALL): release REDs + acq_rel ticket.
        asm volatile("red.add.release.gpu.f32 [%0], %1;"
                     :: "l"(&g_total), "f"(t) : "memory");
        asm volatile("red.add.release.gpu.u32 [%0], %1;"
                     :: "l"(&g_count), "r"(c) : "memory");
        unsigned ticket;
        asm volatile("atom.add.acq_rel.gpu.u32 %0, [%1], %2;"
                     : "=r"(ticket) : "l"(&g_arrive), "r"(1u) : "memory");
        if (ticket == (unsigned)gridDim.x - 1u) {
            float tv; unsigned cv;
            asm volatile("ld.acquire.gpu.f32 %0, [%1];"
                         : "=f"(tv) : "l"(&g_total) : "memory");
            asm volatile("ld.acquire.gpu.u32 %0, [%1];"
                         : "=r"(cv) : "l"(&g_count) : "memory");
            out[0] = (cv > 0u) ? (tv / (float)cv) : 0.0f;
            g_total = 0.0f; g_count = 0u; g_arrive = 0u;
        }
    }
}

// ---------------------------------------------------------------------------
// Generic fallback (round-5 proven kernel), used only if shape differs.
// ---------------------------------------------------------------------------
#define GWARPS 16
#define GTHREADS (GWARPS * 32)

__global__ void __launch_bounds__(GTHREADS, 4)
mpcl_generic_kernel(const float* __restrict__ scores,
                    const int*   __restrict__ pos_indices,
                    const int*   __restrict__ neg_indices,
                    const int*   __restrict__ pos_counts,
                    const int*   __restrict__ neg_counts,
                    float*       __restrict__ out,
                    int B, int C, int P, int N, int nPairs)
{
    __shared__ float    s_tot[GWARPS];
    __shared__ unsigned s_cnt[GWARPS];

    const int warp    = threadIdx.x >> 5;
    const int lane    = threadIdx.x & 31;
    const int gwarp   = blockIdx.x * GWARPS + warp;
    const int wstride = gridDim.x * GWARPS;
    const bool loHalf = (lane < 16);

    float    acc0 = 0.0f, acc1 = 0.0f;
    unsigned cnt  = 0u;

    for (int q = gwarp; q < nPairs; q += wstride) {
        const int  b0   = q * 2;
        const int  b1   = b0 + 1;
        const bool has1 = (b1 < B);

        const int pc0 = min(pos_counts[b0], 16);
        const int nc0 = neg_counts[b0];
        const int pc1 = has1 ? min(pos_counts[b1], 16) : 0;
        const int nc1 = has1 ? neg_counts[b1]          : 0;

        const float* s0  = scores + (size_t)b0 * (size_t)C;
        const float* s1  = scores + (size_t)b1 * (size_t)C;
        const int*   n0p = neg_indices + (size_t)b0 * (size_t)N;
        const int*   n1p = neg_indices + (size_t)b1 * (size_t)N;

        const int    slot  = lane & 15;
        const bool   myOk  = loHalf || has1;
        const int*   pbase = loHalf ? (pos_indices + (size_t)b0 * (size_t)P)
                                    : (pos_indices + (size_t)b1 * (size_t)P);
        const int    jp    = (myOk && slot < P) ? pbase[slot] : 0;
        const float* sbase = loHalf ? s0 : s1;
        float pv = myOk ? sbase[jp] : 1e30f;
        const int pcOwn = loHalf ? pc0 : pc1;
        pv = (slot < pcOwn) ? pv : 1e30f;

        const int j00 = (lane      < N) ? n0p[lane]      : 0;
        const int j01 = (lane + 32 < N) ? n0p[lane + 32] : 0;
        float n00 = (lane      < nc0) ? s0[j00] : -1e30f;
        float n01 = (lane + 32 < nc0) ? s0[j01] : -1e30f;

        float n10 = -1e30f, n11 = -1e30f;
        if (has1) {
            const int j10 = (lane      < N) ? n1p[lane]      : 0;
            const int j11 = (lane + 32 < N) ? n1p[lane + 32] : 0;
            n10 = (lane      < nc1) ? s1[j10] : -1e30f;
            n11 = (lane + 32 < nc1) ? s1[j11] : -1e30f;
        }

        cnt += (unsigned)(pc0 * nc0) + (unsigned)(pc1 * nc1);

        const int it0 = (nc0 > 0) ? pc0 : 0;
        for (int pg = 0; pg < it0; pg += 4) {
            const float x0 = __shfl_sync(0xffffffffu, pv, pg + 0);
            const float x1 = __shfl_sync(0xffffffffu, pv, pg + 1);
            const float x2 = __shfl_sync(0xffffffffu, pv, pg + 2);
            const float x3 = __shfl_sync(0xffffffffu, pv, pg + 3);
            const float a0 = MARGIN - x0, a1 = MARGIN - x1;
            const float a2 = MARGIN - x2, a3 = MARGIN - x3;
            acc0 += fmaxf(a0 + n00, 0.0f) + fmaxf(a1 + n00, 0.0f)
                  + fmaxf(a2 + n00, 0.0f) + fmaxf(a3 + n00, 0.0f);
            acc1 += fmaxf(a0 + n01, 0.0f) + fmaxf(a1 + n01, 0.0f)
                  + fmaxf(a2 + n01, 0.0f) + fmaxf(a3 + n01, 0.0f);
        }
        const int it1 = (nc1 > 0) ? pc1 : 0;
        for (int pg = 0; pg < it1; pg += 4) {
            const float x0 = __shfl_sync(0xffffffffu, pv, 16 + pg + 0);
            const float x1 = __shfl_sync(0xffffffffu, pv, 16 + pg + 1);
            const float x2 = __shfl_sync(0xffffffffu, pv, 16 + pg + 2);
            const float x3 = __shfl_sync(0xffffffffu, pv, 16 + pg + 3);
            const float a0 = MARGIN - x0, a1 = MARGIN - x1;
            const float a2 = MARGIN - x2, a3 = MARGIN - x3;
            acc0 += fmaxf(a0 + n10, 0.0f) + fmaxf(a1 + n10, 0.0f)
                  + fmaxf(a2 + n10, 0.0f) + fmaxf(a3 + n10, 0.0f);
            acc1 += fmaxf(a0 + n11, 0.0f) + fmaxf(a1 + n11, 0.0f)
                  + fmaxf(a2 + n11, 0.0f) + fmaxf(a3 + n11, 0.0f);
        }
    }

    float accs = acc0 + acc1;
    #pragma unroll
    for (int o = 16; o > 0; o >>= 1)
        accs += __shfl_xor_sync(0xffffffffu, accs, o);

    if (lane == 0) { s_tot[warp] = accs; s_cnt[warp] = cnt; }
    __syncthreads();

    if (threadIdx.x == 0) {
        float    t = 0.0f;
        unsigned c = 0u;
        #pragma unroll
        for (int i = 0; i < GWARPS; i++) { t += s_tot[i]; c += s_cnt[i]; }
        asm volatile("red.add.release.gpu.f32 [%0], %1;"
                     :: "l"(&g_total), "f"(t) : "memory");
        asm volatile("red.add.release.gpu.u32 [%0], %1;"
                     :: "l"(&g_count), "r"(c) : "memory");
        unsigned ticket;
        asm volatile("atom.add.acq_rel.gpu.u32 %0, [%1], %2;"
                     : "=r"(ticket) : "l"(&g_arrive), "r"(1u) : "memory");
        if (ticket == (unsigned)gridDim.x - 1u) {
            float tv; unsigned cv;
            asm volatile("ld.acquire.gpu.f32 %0, [%1];"
                         : "=f"(tv) : "l"(&g_total) : "memory");
            asm volatile("ld.acquire.gpu.u32 %0, [%1];"
                         : "=r"(cv) : "l"(&g_count) : "memory");
            out[0] = (cv > 0u) ? (tv / (float)cv) : 0.0f;
            g_total = 0.0f; g_count = 0u; g_arrive = 0u;
        }
    }
}

extern "C" void kernel_launch(void* const* d_in, const int* in_sizes, int n_in,
                              void* d_out, int out_size)
{
    const float* scores      = (const float*)d_in[0];
    const int*   pos_indices = (const int*)  d_in[1];
    const int*   neg_indices = (const int*)  d_in[2];
    const int*   pos_counts  = (const int*)  d_in[3];
    const int*   neg_counts  = (const int*)  d_in[4];
    float*       out         = (float*)d_out;

    const int B = in_sizes[3];
    const int C = in_sizes[0] / B;
    const int P = in_sizes[1] / B;
    const int N = in_sizes[2] / B;

    if (C == 64 && P == 16 && N == 48 && (B % 32) == 0) {
        const int blocks = B / 32;
        mpcl_fast_kernel<<<blocks, FTHREADS>>>(
            scores, pos_indices, neg_indices, pos_counts, neg_counts, out);
    } else {
        const int nPairs = (B + 1) / 2;
        int blocks = (nPairs + GWARPS * 2 - 1) / (GWARPS * 2);
        if (blocks > 592) blocks = 592;
        if (blocks < 1)   blocks = 1;
        mpcl_generic_kernel<<<blocks, GTHREADS>>>(
            scores, pos_indices, neg_indices, pos_counts, neg_counts, out,
            B, C, P, N, nPairs);
    }
}